// round 16
// baseline (speedup 1.0000x reference)
#include <cuda_runtime.h>
#include <cuda_bf16.h>
#include <math.h>
#include <stdint.h>

#define T_SEQ 2048
#define D_MODEL 1024
#define N_HEADS 16
#define HEAD_DIM 64
#define FFN_DIM 4096
typedef __nv_bfloat16 bf16;

// ---------------- scratch ----------------
__device__ float g_x1[T_SEQ * D_MODEL];
__device__ bf16  g_xnh[T_SEQ * D_MODEL], g_xnl[T_SEQ * D_MODEL];
__device__ bf16  g_qh[T_SEQ * D_MODEL], g_ql[T_SEQ * D_MODEL];
__device__ bf16  g_kh[T_SEQ * D_MODEL], g_kl[T_SEQ * D_MODEL];
__device__ bf16  g_vh[T_SEQ * D_MODEL], g_vl[T_SEQ * D_MODEL];
__device__ bf16  g_ah[T_SEQ * D_MODEL], g_al[T_SEQ * D_MODEL];
__device__ bf16  g_hh[T_SEQ * FFN_DIM], g_hl[T_SEQ * FFN_DIM];
__device__ bf16 g_wqh[D_MODEL * D_MODEL], g_wql[D_MODEL * D_MODEL];
__device__ bf16 g_wkh[D_MODEL * D_MODEL], g_wkl[D_MODEL * D_MODEL];
__device__ bf16 g_wvh[D_MODEL * D_MODEL], g_wvl[D_MODEL * D_MODEL];
__device__ bf16 g_woh[D_MODEL * D_MODEL], g_wol[D_MODEL * D_MODEL];
__device__ bf16 g_w1h[FFN_DIM * D_MODEL], g_w1l[FFN_DIM * D_MODEL];
__device__ bf16 g_w2h[D_MODEL * FFN_DIM], g_w2l[D_MODEL * FFN_DIM];

// ---------------- helpers ----------------
__device__ __forceinline__ uint32_t smem_u32(const void* p) {
    uint32_t a;
    asm("{ .reg .u64 t; cvta.to.shared.u64 t, %1; cvt.u32.u64 %0, t; }" : "=r"(a) : "l"(p));
    return a;
}
__device__ __forceinline__ void cp16(uint32_t s, const void* g) {
    asm volatile("cp.async.cg.shared.global [%0], [%1], 16;" :: "r"(s), "l"(g));
}
#define CP_COMMIT() asm volatile("cp.async.commit_group;" ::: "memory")
#define CP_WAIT(n)  asm volatile("cp.async.wait_group %0;" :: "n"(n) : "memory")

__device__ __forceinline__ void ldsm4(uint32_t* r, uint32_t addr) {
    asm volatile("ldmatrix.sync.aligned.m8n8.x4.shared.b16 {%0,%1,%2,%3}, [%4];"
        : "=r"(r[0]), "=r"(r[1]), "=r"(r[2]), "=r"(r[3]) : "r"(addr));
}
__device__ __forceinline__ void ldsm4t(uint32_t* r, uint32_t addr) {
    asm volatile("ldmatrix.sync.aligned.m8n8.x4.trans.shared.b16 {%0,%1,%2,%3}, [%4];"
        : "=r"(r[0]), "=r"(r[1]), "=r"(r[2]), "=r"(r[3]) : "r"(addr));
}
__device__ __forceinline__ void mma_bf16(float* d, const uint32_t* a, const uint32_t* b) {
    asm volatile(
        "mma.sync.aligned.m16n8k16.row.col.f32.bf16.bf16.f32 "
        "{%0,%1,%2,%3}, {%4,%5,%6,%7}, {%8,%9}, {%0,%1,%2,%3};"
        : "+f"(d[0]), "+f"(d[1]), "+f"(d[2]), "+f"(d[3])
        : "r"(a[0]), "r"(a[1]), "r"(a[2]), "r"(a[3]), "r"(b[0]), "r"(b[1]));
}
__device__ __forceinline__ uint32_t bfpack(float a, float b) {
    __nv_bfloat162 t = __floats2bfloat162_rn(a, b);
    return *reinterpret_cast<uint32_t*>(&t);
}
__device__ __forceinline__ float bfhi(float v) {
    return __bfloat162float(__float2bfloat16(v));
}
__device__ __forceinline__ float ex2(float x) {
    float y;
    asm("ex2.approx.ftz.f32 %0, %1;" : "=f"(y) : "f"(x));
    return y;
}

// ---------------- batched weight splits ----------------
__global__ void wsplit4(const float* __restrict__ Wq, const float* __restrict__ Wk,
                        const float* __restrict__ Wv, const float* __restrict__ Wo,
                        bf16* __restrict__ Hq, bf16* __restrict__ Lq,
                        bf16* __restrict__ Hk, bf16* __restrict__ Lk,
                        bf16* __restrict__ Hv, bf16* __restrict__ Lv,
                        bf16* __restrict__ Ho, bf16* __restrict__ Lo) {
    const int m = blockIdx.y;
    const float* W = (m == 0) ? Wq : (m == 1) ? Wk : (m == 2) ? Wv : Wo;
    bf16* H = (m == 0) ? Hq : (m == 1) ? Hk : (m == 2) ? Hv : Ho;
    bf16* L = (m == 0) ? Lq : (m == 1) ? Lk : (m == 2) ? Lv : Lo;
    const size_t base = ((size_t)blockIdx.x * 4096) + threadIdx.x * 4;
    float4 v[4];
    #pragma unroll
    for (int j = 0; j < 4; ++j) v[j] = *(const float4*)&W[base + j * 1024];
    #pragma unroll
    for (int j = 0; j < 4; ++j) {
        uint2 hh, ll;
        hh.x = bfpack(v[j].x, v[j].y); hh.y = bfpack(v[j].z, v[j].w);
        ll.x = bfpack(v[j].x - bfhi(v[j].x), v[j].y - bfhi(v[j].y));
        ll.y = bfpack(v[j].z - bfhi(v[j].z), v[j].w - bfhi(v[j].w));
        *(uint2*)&H[base + j * 1024] = hh;
        *(uint2*)&L[base + j * 1024] = ll;
    }
}
__global__ void wsplit2(const float* __restrict__ W1, const float* __restrict__ W2,
                        bf16* __restrict__ H1, bf16* __restrict__ L1,
                        bf16* __restrict__ H2, bf16* __restrict__ L2) {
    const int m = blockIdx.y;
    const float* W = (m == 0) ? W1 : W2;
    bf16* H = (m == 0) ? H1 : H2;
    bf16* L = (m == 0) ? L1 : L2;
    const size_t base = ((size_t)blockIdx.x * 4096) + threadIdx.x * 4;
    float4 v[4];
    #pragma unroll
    for (int j = 0; j < 4; ++j) v[j] = *(const float4*)&W[base + j * 1024];
    #pragma unroll
    for (int j = 0; j < 4; ++j) {
        uint2 hh, ll;
        hh.x = bfpack(v[j].x, v[j].y); hh.y = bfpack(v[j].z, v[j].w);
        ll.x = bfpack(v[j].x - bfhi(v[j].x), v[j].y - bfhi(v[j].y));
        ll.y = bfpack(v[j].z - bfhi(v[j].z), v[j].w - bfhi(v[j].w));
        *(uint2*)&H[base + j * 1024] = hh;
        *(uint2*)&L[base + j * 1024] = ll;
    }
}

// ---------------- LayerNorm -> bf16 hi/lo ----------------
__global__ void ln_kernel(const float* __restrict__ x, const float* __restrict__ g,
                          const float* __restrict__ b, bf16* __restrict__ yh,
                          bf16* __restrict__ yl) {
    const int row = blockIdx.x, tid = threadIdx.x;
    const float4 xv = *(const float4*)&x[(size_t)row * D_MODEL + tid * 4];
    float s  = (xv.x + xv.y) + (xv.z + xv.w);
    float s2 = (xv.x * xv.x + xv.y * xv.y) + (xv.z * xv.z + xv.w * xv.w);
    __shared__ float red0[8], red1[8];
    #pragma unroll
    for (int o = 16; o > 0; o >>= 1) {
        s  += __shfl_down_sync(0xffffffffu, s, o);
        s2 += __shfl_down_sync(0xffffffffu, s2, o);
    }
    const int w = tid >> 5, l = tid & 31;
    if (l == 0) { red0[w] = s; red1[w] = s2; }
    __syncthreads();
    if (w == 0) {
        s  = (l < 8) ? red0[l] : 0.f;
        s2 = (l < 8) ? red1[l] : 0.f;
        #pragma unroll
        for (int o = 4; o > 0; o >>= 1) {
            s  += __shfl_down_sync(0xffffffffu, s, o);
            s2 += __shfl_down_sync(0xffffffffu, s2, o);
        }
        if (l == 0) { red0[0] = s; red1[0] = s2; }
    }
    __syncthreads();
    const float mu  = red0[0] * (1.f / D_MODEL);
    const float var = red1[0] * (1.f / D_MODEL) - mu * mu;
    const float inv = rsqrtf(var + 1e-5f);
    const float4 gv = *(const float4*)&g[tid * 4];
    const float4 bv = *(const float4*)&b[tid * 4];
    float o0 = (xv.x - mu) * inv * gv.x + bv.x;
    float o1 = (xv.y - mu) * inv * gv.y + bv.y;
    float o2 = (xv.z - mu) * inv * gv.z + bv.z;
    float o3 = (xv.w - mu) * inv * gv.w + bv.w;
    uint2 H, L;
    H.x = bfpack(o0, o1); H.y = bfpack(o2, o3);
    L.x = bfpack(o0 - bfhi(o0), o1 - bfhi(o1));
    L.y = bfpack(o2 - bfhi(o2), o3 - bfhi(o3));
    *(uint2*)&yh[(size_t)row * D_MODEL + tid * 4] = H;
    *(uint2*)&yl[(size_t)row * D_MODEL + tid * 4] = L;
}

// ---------------- bf16x3 mma GEMM with ldmatrix ----------------
// BM=128: warp tile 32x(BN/2), MT=2. BM=64: warp tile 16x(BN/2), MT=1 (grid doubles).
template<int ACT, bool HAS_RES, bool OUT_HILO, int BM, int BN, int OCC>
__global__ void __launch_bounds__(256, OCC)
bgemm(const bf16* __restrict__ Ah, const bf16* __restrict__ Al,
      const bf16* __restrict__ W0h, const bf16* __restrict__ W0l,
      const bf16* __restrict__ W1h, const bf16* __restrict__ W1l,
      const bf16* __restrict__ W2h, const bf16* __restrict__ W2l,
      const float* __restrict__ b0, const float* __restrict__ b1, const float* __restrict__ b2,
      const float* __restrict__ Res,
      void* __restrict__ C0, void* __restrict__ C1, void* __restrict__ C2,
      void* __restrict__ Cl0, void* __restrict__ Cl1, void* __restrict__ Cl2,
      int N, int K) {
    constexpr int KB     = (BM == 64) ? 64 : 32;          // BM=128/OCC=3 -> KB=32
    constexpr int KSTEPS = KB / 16;
    constexpr int MT     = BM / 64;
    constexpr int A_STR  = KB * 2 + 16;
    constexpr int B_STR  = BN * 2 + 16;
    constexpr int ARR_A  = BM * A_STR;
    constexpr int ARR_B  = KB * B_STR;
    constexpr int STAGE  = 2 * ARR_A + 2 * ARR_B;
    constexpr int NT     = BN / 16;
    constexpr int NPAIR  = NT / 2;

    extern __shared__ char smem[];
    const int z = blockIdx.z;
    const bf16* Wh    = (z == 0) ? W0h : (z == 1) ? W1h : W2h;
    const bf16* Wl    = (z == 0) ? W0l : (z == 1) ? W1l : W2l;
    const float* bias = (z == 0) ? b0 : (z == 1) ? b1 : b2;
    void* Cv          = (z == 0) ? C0 : (z == 1) ? C1 : C2;
    void* Clv         = (z == 0) ? Cl0 : (z == 1) ? Cl1 : Cl2;

    const int m0 = blockIdx.y * BM;
    const int n0 = blockIdx.x * BN;
    const int tid = threadIdx.x;
    const int wid = tid >> 5, lane = tid & 31;
    const int wrow = wid & 3, wcol = wid >> 2;
    const int lr = lane >> 2, lc = lane & 3;
    const int lrow = lane & 7, sub = lane >> 3;

    const uint32_t sbase = smem_u32(smem);
    const int NKB = K / KB;

    const uint32_t aoff = (uint32_t)(wrow * (BM / 4) + lrow + 8 * (sub & 1)) * (uint32_t)A_STR + 16u * (sub >> 1);
    const uint32_t boff = (uint32_t)(lrow + 8 * (sub & 1)) * (uint32_t)B_STR +
                          (uint32_t)(wcol * (BN / 2) + 8 * (sub >> 1)) * 2u;

    auto load_stage = [&](int kb, int s) {
        const int k0 = kb * KB;
        const uint32_t st = sbase + s * STAGE;
        #pragma unroll
        for (int f = tid; f < BM * (KB / 8); f += 256) {
            const int r = f / (KB / 8), cc = f % (KB / 8);
            const uint32_t doff = (uint32_t)r * (uint32_t)A_STR + (uint32_t)cc * 16u;
            const size_t go = (size_t)(m0 + r) * K + k0 + cc * 8;
            cp16(st + doff, Ah + go);
            cp16(st + ARR_A + doff, Al + go);
        }
        #pragma unroll
        for (int f = tid; f < KB * (BN / 8); f += 256) {
            const int r = f / (BN / 8), cc = f % (BN / 8);
            const uint32_t doff = (uint32_t)r * (uint32_t)B_STR + (uint32_t)cc * 16u;
            const size_t go = (size_t)(k0 + r) * N + n0 + cc * 8;
            cp16(st + 2 * ARR_A + doff, Wh + go);
            cp16(st + 2 * ARR_A + ARR_B + doff, Wl + go);
        }
    };

    float acc[MT][NT][4];
    #pragma unroll
    for (int mt = 0; mt < MT; ++mt)
        #pragma unroll
        for (int nt = 0; nt < NT; ++nt)
            #pragma unroll
            for (int i = 0; i < 4; ++i) acc[mt][nt][i] = 0.f;

    auto domma = [&](int s) {
        const uint32_t stg = sbase + s * STAGE;
        #pragma unroll
        for (int kstep = 0; kstep < KSTEPS; ++kstep) {
            uint32_t ah[MT][4], al[MT][4];
            #pragma unroll
            for (int mt = 0; mt < MT; ++mt) {
                ldsm4(ah[mt], stg + aoff + mt * 16 * A_STR + kstep * 32);
                ldsm4(al[mt], stg + ARR_A + aoff + mt * 16 * A_STR + kstep * 32);
            }
            uint32_t bh[NT][2], bl[NT][2];
            #pragma unroll
            for (int p = 0; p < NPAIR; ++p) {
                uint32_t t[4];
                ldsm4t(t, stg + 2 * ARR_A + boff + p * 32 + kstep * 16 * B_STR);
                bh[2 * p][0] = t[0]; bh[2 * p][1] = t[1];
                bh[2 * p + 1][0] = t[2]; bh[2 * p + 1][1] = t[3];
                ldsm4t(t, stg + 2 * ARR_A + ARR_B + boff + p * 32 + kstep * 16 * B_STR);
                bl[2 * p][0] = t[0]; bl[2 * p][1] = t[1];
                bl[2 * p + 1][0] = t[2]; bl[2 * p + 1][1] = t[3];
            }
            #pragma unroll
            for (int nt = 0; nt < NT; ++nt)
                #pragma unroll
                for (int mt = 0; mt < MT; ++mt) {
                    mma_bf16(acc[mt][nt], ah[mt], bh[nt]);
                    mma_bf16(acc[mt][nt], al[mt], bh[nt]);
                    mma_bf16(acc[mt][nt], ah[mt], bl[nt]);
                }
        }
    };

    load_stage(0, 0);
    CP_COMMIT();
    for (int kb = 0; kb < NKB; ++kb) {
        const int s = kb & 1;
        CP_WAIT(0);
        __syncthreads();
        if (kb + 1 < NKB) {
            load_stage(kb + 1, s ^ 1);
            CP_COMMIT();
        }
        domma(s);
    }

    #pragma unroll
    for (int nt = 0; nt < NT; ++nt) {
        const int col = n0 + wcol * (BN / 2) + nt * 8 + lc * 2;
        const float2 bv = *(const float2*)&bias[col];
        #pragma unroll
        for (int mt = 0; mt < MT; ++mt) {
            const int row = m0 + wrow * (BM / 4) + mt * 16 + lr;
            #pragma unroll
            for (int half = 0; half < 2; ++half) {
                const int r = row + half * 8;
                float vx = acc[mt][nt][half * 2 + 0] + bv.x;
                float vy = acc[mt][nt][half * 2 + 1] + bv.y;
                if (ACT == 1) {
                    vx = 0.5f * vx * (1.0f + erff(vx * 0.7071067811865475f));
                    vy = 0.5f * vy * (1.0f + erff(vy * 0.7071067811865475f));
                }
                if (HAS_RES) {
                    float2 rv = *(const float2*)&Res[(size_t)r * N + col];
                    vx += rv.x; vy += rv.y;
                }
                if (OUT_HILO) {
                    bf16* Ch = (bf16*)Cv;
                    bf16* Cl = (bf16*)Clv;
                    *(uint32_t*)&Ch[(size_t)r * N + col] = bfpack(vx, vy);
                    *(uint32_t*)&Cl[(size_t)r * N + col] =
                        bfpack(vx - bfhi(vx), vy - bfhi(vy));
                } else {
                    float2 o; o.x = vx; o.y = vy;
                    *(float2*)&((float*)Cv)[(size_t)r * N + col] = o;
                }
            }
        }
    }
}

// ---------------- flash attention v4: 64-row q-tiles, 2 CTAs/SM ----------------
#define AS_KH(s)  ((s) * 36864 + 0)
#define AS_KL(s)  ((s) * 36864 + 9216)
#define AS_VH(s)  ((s) * 36864 + 18432)
#define AS_VL(s)  ((s) * 36864 + 27648)
#define AS_QH     73728
#define AS_QL     82944
#define AS_PMAX   92160
#define SMEM_ATT2 93184

__global__ void __launch_bounds__(256, 2)
attn2(const bf16* __restrict__ Qh, const bf16* __restrict__ Ql,
      const bf16* __restrict__ Kh, const bf16* __restrict__ Kl,
      const bf16* __restrict__ Vh, const bf16* __restrict__ Vl,
      bf16* __restrict__ OH, bf16* __restrict__ OL) {
    extern __shared__ char smc[];
    const uint32_t sb = smem_u32(smc);
    const int qb = gridDim.x - 1 - blockIdx.x;
    const int h  = blockIdx.y;
    const int tid = threadIdx.x;
    const int wid = tid >> 5, lane = tid & 31;
    const int wrow = wid & 1, wcol = wid >> 1;
    const int lr = lane >> 2, lc = lane & 3;
    const int lrow = lane & 7, sub = lane >> 3;

    float* pmax = (float*)(smc + AS_PMAX);

    #pragma unroll
    for (int i = 0; i < 2; ++i) {
        const int f = tid + i * 256;
        const int r = f >> 3, c = f & 7;
        const size_t go = (size_t)(qb * 64 + r) * D_MODEL + h * 64 + c * 8;
        cp16(sb + AS_QH + r * 144 + c * 16, Qh + go);
        cp16(sb + AS_QL + r * 144 + c * 16, Ql + go);
    }
    auto load_kv = [&](int kb, int s) {
        #pragma unroll
        for (int i = 0; i < 2; ++i) {
            const int f = tid + i * 256;
            const int r = f >> 3, c = f & 7;
            const size_t go = (size_t)(kb * 64 + r) * D_MODEL + h * 64 + c * 8;
            cp16(sb + AS_KH(s) + r * 144 + c * 16, Kh + go);
            cp16(sb + AS_KL(s) + r * 144 + c * 16, Kl + go);
            cp16(sb + AS_VH(s) + r * 144 + c * 16, Vh + go);
            cp16(sb + AS_VL(s) + r * 144 + c * 16, Vl + go);
        }
    };
    load_kv(0, 0);
    CP_COMMIT();

    const float QS = 0.125f * 1.4426950408889634f;
    const float slope2 = 1.4426950408889634f * exp2f(-0.5f * (float)(h + 1));
    float oacc[2][8][4] = {};
    float m_reg[2][2] = {{-1e30f, -1e30f}, {-1e30f, -1e30f}};
    float l_reg[2][2] = {};

    const uint32_t aoffQ = sb + AS_QH + (uint32_t)(wrow * 32 + lrow + 8 * (sub & 1)) * 144u + 16u * (sub >> 1);
    const uint32_t bSoff = (uint32_t)(16 * wcol + lrow + 8 * (sub >> 1)) * 144u + 16u * (sub & 1);
    const uint32_t bVoff = (uint32_t)(16 * wcol + lrow + 8 * (sub & 1)) * 144u + (uint32_t)(8 * (sub >> 1)) * 2u;

    const int nkb = qb + 1;
    for (int kb = 0; kb < nkb; ++kb) {
        const int s = kb & 1;
        CP_WAIT(0);
        __syncthreads();
        if (kb + 1 < nkb) { load_kv(kb + 1, s ^ 1); CP_COMMIT(); }

        float sacc[2][2][4] = {};
        #pragma unroll
        for (int ks = 0; ks < 4; ++ks) {
            uint32_t qhf[2][4], qlf[2][4];
            #pragma unroll
            for (int mt = 0; mt < 2; ++mt) {
                ldsm4(qhf[mt], aoffQ + mt * 2304 + ks * 32);
                ldsm4(qlf[mt], aoffQ + 9216 + mt * 2304 + ks * 32);
            }
            uint32_t khf[2][2], klf[2][2], t[4];
            ldsm4(t, sb + AS_KH(s) + bSoff + ks * 32);
            khf[0][0] = t[0]; khf[0][1] = t[1]; khf[1][0] = t[2]; khf[1][1] = t[3];
            ldsm4(t, sb + AS_KL(s) + bSoff + ks * 32);
            klf[0][0] = t[0]; klf[0][1] = t[1]; klf[1][0] = t[2]; klf[1][1] = t[3];
            #pragma unroll
            for (int nt = 0; nt < 2; ++nt) {
                mma_bf16(sacc[0][nt], qhf[0], khf[nt]);
                mma_bf16(sacc[1][nt], qhf[1], khf[nt]);
                mma_bf16(sacc[0][nt], qlf[0], khf[nt]);
                mma_bf16(sacc[1][nt], qlf[1], khf[nt]);
                mma_bf16(sacc[0][nt], qhf[0], klf[nt]);
                mma_bf16(sacc[1][nt], qhf[1], klf[nt]);
            }
        }

        const bool diag = (kb == qb);
        #pragma unroll
        for (int mt = 0; mt < 2; ++mt) {
            const int ra = qb * 64 + wrow * 32 + mt * 16 + lr, rb = ra + 8;
            float ma = -1e30f, mb = -1e30f;
            #pragma unroll
            for (int nt = 0; nt < 2; ++nt) {
                const int c0 = kb * 64 + 16 * wcol + 8 * nt + 2 * lc;
                float* sv = sacc[mt][nt];
                if (diag) {
                    sv[0] = (c0     <= ra) ? fmaf(sv[0], QS, slope2 * (float)(c0 - ra))     : -1e30f;
                    sv[1] = (c0 + 1 <= ra) ? fmaf(sv[1], QS, slope2 * (float)(c0 + 1 - ra)) : -1e30f;
                    sv[2] = (c0     <= rb) ? fmaf(sv[2], QS, slope2 * (float)(c0 - rb))     : -1e30f;
                    sv[3] = (c0 + 1 <= rb) ? fmaf(sv[3], QS, slope2 * (float)(c0 + 1 - rb)) : -1e30f;
                } else {
                    sv[0] = fmaf(sv[0], QS, slope2 * (float)(c0 - ra));
                    sv[1] = fmaf(sv[1], QS, slope2 * (float)(c0 + 1 - ra));
                    sv[2] = fmaf(sv[2], QS, slope2 * (float)(c0 - rb));
                    sv[3] = fmaf(sv[3], QS, slope2 * (float)(c0 + 1 - rb));
                }
                ma = fmaxf(ma, fmaxf(sv[0], sv[1]));
                mb = fmaxf(mb, fmaxf(sv[2], sv[3]));
            }
            ma = fmaxf(ma, __shfl_xor_sync(0xffffffffu, ma, 1));
            ma = fmaxf(ma, __shfl_xor_sync(0xffffffffu, ma, 2));
            mb = fmaxf(mb, __shfl_xor_sync(0xffffffffu, mb, 1));
            mb = fmaxf(mb, __shfl_xor_sync(0xffffffffu, mb, 2));
            if (lc == 0) {
                pmax[wcol * 64 + wrow * 32 + mt * 16 + lr]     = ma;
                pmax[wcol * 64 + wrow * 32 + mt * 16 + lr + 8] = mb;
            }
        }
        __syncthreads();

        float alpha[2][2];
        #pragma unroll
        for (int mt = 0; mt < 2; ++mt) {
            const int rla = wrow * 32 + mt * 16 + lr, rlb = rla + 8;
            const float pa = fmaxf(fmaxf(pmax[rla], pmax[64 + rla]),
                                   fmaxf(pmax[128 + rla], pmax[192 + rla]));
            const float pb = fmaxf(fmaxf(pmax[rlb], pmax[64 + rlb]),
                                   fmaxf(pmax[128 + rlb], pmax[192 + rlb]));
            const float mna = fmaxf(m_reg[mt][0], pa);
            const float mnb = fmaxf(m_reg[mt][1], pb);
            alpha[mt][0] = ex2(m_reg[mt][0] - mna);
            alpha[mt][1] = ex2(m_reg[mt][1] - mnb);
            m_reg[mt][0] = mna; m_reg[mt][1] = mnb;
        }
        #pragma unroll
        for (int mt = 0; mt < 2; ++mt) {
            float sa = 0.f, sbv = 0.f;
            #pragma unroll
            for (int nt = 0; nt < 2; ++nt) {
                float* sv = sacc[mt][nt];
                sv[0] = ex2(sv[0] - m_reg[mt][0]); sv[1] = ex2(sv[1] - m_reg[mt][0]);
                sv[2] = ex2(sv[2] - m_reg[mt][1]); sv[3] = ex2(sv[3] - m_reg[mt][1]);
                sa += sv[0] + sv[1]; sbv += sv[2] + sv[3];
            }
            sa  += __shfl_xor_sync(0xffffffffu, sa, 1);
            sa  += __shfl_xor_sync(0xffffffffu, sa, 2);
            sbv += __shfl_xor_sync(0xffffffffu, sbv, 1);
            sbv += __shfl_xor_sync(0xffffffffu, sbv, 2);
            l_reg[mt][0] = l_reg[mt][0] * alpha[mt][0] + sa;
            l_reg[mt][1] = l_reg[mt][1] * alpha[mt][1] + sbv;
        }
        #pragma unroll
        for (int mt = 0; mt < 2; ++mt)
            #pragma unroll
            for (int nt = 0; nt < 8; ++nt) {
                oacc[mt][nt][0] *= alpha[mt][0]; oacc[mt][nt][1] *= alpha[mt][0];
                oacc[mt][nt][2] *= alpha[mt][1]; oacc[mt][nt][3] *= alpha[mt][1];
            }

        uint32_t pah[2][4], pal[2][4];
        #pragma unroll
        for (int mt = 0; mt < 2; ++mt) {
            const float* s0 = sacc[mt][0];
            const float* s1 = sacc[mt][1];
            pah[mt][0] = bfpack(s0[0], s0[1]); pah[mt][1] = bfpack(s0[2], s0[3]);
            pah[mt][2] = bfpack(s1[0], s1[1]); pah[mt][3] = bfpack(s1[2], s1[3]);
            pal[mt][0] = bfpack(s0[0] - bfhi(s0[0]), s0[1] - bfhi(s0[1]));
            pal[mt][1] = bfpack(s0[2] - bfhi(s0[2]), s0[3] - bfhi(s0[3]));
            pal[mt][2] = bfpack(s1[0] - bfhi(s1[0]), s1[1] - bfhi(s1[1]));
            pal[mt][3] = bfpack(s1[2] - bfhi(s1[2]), s1[3] - bfhi(s1[3]));
        }
        #pragma unroll
        for (int p = 0; p < 4; ++p) {
            uint32_t vh[2][2], vl[2][2], t[4];
            ldsm4t(t, sb + AS_VH(s) + bVoff + p * 32);
            vh[0][0] = t[0]; vh[0][1] = t[1]; vh[1][0] = t[2]; vh[1][1] = t[3];
            ldsm4t(t, sb + AS_VL(s) + bVoff + p * 32);
            vl[0][0] = t[0]; vl[0][1] = t[1]; vl[1][0] = t[2]; vl[1][1] = t[3];
            #pragma unroll
            for (int q2 = 0; q2 < 2; ++q2) {
                const int nt = 2 * p + q2;
                mma_bf16(oacc[0][nt], pah[0], vh[q2]);
                mma_bf16(oacc[1][nt], pah[1], vh[q2]);
                mma_bf16(oacc[0][nt], pal[0], vh[q2]);
                mma_bf16(oacc[1][nt], pal[1], vh[q2]);
                mma_bf16(oacc[0][nt], pah[0], vl[q2]);
                mma_bf16(oacc[1][nt], pah[1], vl[q2]);
            }
        }
    }

    __syncthreads();
    if (lc == 0) {
        #pragma unroll
        for (int mt = 0; mt < 2; ++mt) {
            pmax[wcol * 64 + wrow * 32 + mt * 16 + lr]     = l_reg[mt][0];
            pmax[wcol * 64 + wrow * 32 + mt * 16 + lr + 8] = l_reg[mt][1];
        }
    }
    float* Ob = (float*)smc;
    #pragma unroll
    for (int w = 0; w < 4; ++w) {
        if (wcol == w) {
            #pragma unroll
            for (int mt = 0; mt < 2; ++mt) {
                const int rla = wrow * 32 + mt * 16 + lr, rlb = rla + 8;
                #pragma unroll
                for (int nt = 0; nt < 8; ++nt) {
                    const int d0 = 8 * nt + 2 * lc;
                    if (w == 0) {
                        Ob[rla * 64 + d0]     = oacc[mt][nt][0];
                        Ob[rla * 64 + d0 + 1] = oacc[mt][nt][1];
                        Ob[rlb * 64 + d0]     = oacc[mt][nt][2];
                        Ob[rlb * 64 + d0 + 1] = oacc[mt][nt][3];
                    } else {
                        Ob[rla * 64 + d0]     += oacc[mt][nt][0];
                        Ob[rla * 64 + d0 + 1] += oacc[mt][nt][1];
                        Ob[rlb * 64 + d0]     += oacc[mt][nt][2];
                        Ob[rlb * 64 + d0 + 1] += oacc[mt][nt][3];
                    }
                }
            }
        }
        __syncthreads();
    }
    #pragma unroll
    for (int i = 0; i < 16; ++i) {
        const int f = tid + i * 256;
        const int r = f >> 6, d = f & 63;
        const float lsum = (pmax[r] + pmax[64 + r]) + (pmax[128 + r] + pmax[192 + r]);
        const float val = Ob[f] / lsum;
        const size_t go = (size_t)(qb * 64 + r) * D_MODEL + h * 64 + d;
        OH[go] = __float2bfloat16(val);
        OL[go] = __float2bfloat16(val - bfhi(val));
    }
}

// ---------------- launch ----------------
extern "C" void kernel_launch(void* const* d_in, const int* in_sizes, int n_in,
                              void* d_out, int out_size) {
    const float* x   = (const float*)d_in[0];
    const float* wq  = (const float*)d_in[3];
    const float* bq  = (const float*)d_in[4];
    const float* wk  = (const float*)d_in[5];
    const float* bk  = (const float*)d_in[6];
    const float* wv  = (const float*)d_in[7];
    const float* bv  = (const float*)d_in[8];
    const float* wo  = (const float*)d_in[9];
    const float* bo  = (const float*)d_in[10];
    const float* w1  = (const float*)d_in[11];
    const float* b1  = (const float*)d_in[12];
    const float* w2  = (const float*)d_in[13];
    const float* b2  = (const float*)d_in[14];
    const float* g1  = (const float*)d_in[15];
    const float* be1 = (const float*)d_in[16];
    const float* g2  = (const float*)d_in[17];
    const float* be2 = (const float*)d_in[18];
    float* out = (float*)d_out;

    float* p_x1;
    bf16 *p_xnh, *p_xnl, *p_ah, *p_al, *p_hh, *p_hl;
    bf16 *p_qh, *p_ql, *p_kh, *p_kl, *p_vh, *p_vl;
    bf16 *p_wqh, *p_wql, *p_wkh, *p_wkl, *p_wvh, *p_wvl, *p_woh, *p_wol;
    bf16 *p_w1h, *p_w1l, *p_w2h, *p_w2l;
    cudaGetSymbolAddress((void**)&p_x1,  g_x1);
    cudaGetSymbolAddress((void**)&p_xnh, g_xnh);
    cudaGetSymbolAddress((void**)&p_xnl, g_xnl);
    cudaGetSymbolAddress((void**)&p_qh,  g_qh);
    cudaGetSymbolAddress((void**)&p_ql,  g_ql);
    cudaGetSymbolAddress((void**)&p_kh,  g_kh);
    cudaGetSymbolAddress((void**)&p_kl,  g_kl);
    cudaGetSymbolAddress((void**)&p_vh,  g_vh);
    cudaGetSymbolAddress((void**)&p_vl,  g_vl);
    cudaGetSymbolAddress((void**)&p_ah,  g_ah);
    cudaGetSymbolAddress((void**)&p_al,  g_al);
    cudaGetSymbolAddress((void**)&p_hh,  g_hh);
    cudaGetSymbolAddress((void**)&p_hl,  g_hl);
    cudaGetSymbolAddress((void**)&p_wqh, g_wqh);
    cudaGetSymbolAddress((void**)&p_wql, g_wql);
    cudaGetSymbolAddress((void**)&p_wkh, g_wkh);
    cudaGetSymbolAddress((void**)&p_wkl, g_wkl);
    cudaGetSymbolAddress((void**)&p_wvh, g_wvh);
    cudaGetSymbolAddress((void**)&p_wvl, g_wvl);
    cudaGetSymbolAddress((void**)&p_woh, g_woh);
    cudaGetSymbolAddress((void**)&p_wol, g_wol);
    cudaGetSymbolAddress((void**)&p_w1h, g_w1h);
    cudaGetSymbolAddress((void**)&p_w1l, g_w1l);
    cudaGetSymbolAddress((void**)&p_w2h, g_w2h);
    cudaGetSymbolAddress((void**)&p_w2l, g_w2l);

    // smem sizes
    const int smem_128_o3 = 2 * (2 * 128 * 80 + 2 * 32 * 144);   // 59392 (BM128 KB32)
    const int smem_64_o3  = 2 * (2 * 64 * 144 + 2 * 64 * 144);   // 73728 (BM64 KB64)

    cudaFuncSetAttribute((const void*)bgemm<0, false, true, 128, 64, 3>, cudaFuncAttributeMaxDynamicSharedMemorySize, smem_128_o3);
    cudaFuncSetAttribute((const void*)bgemm<1, false, true, 128, 64, 3>, cudaFuncAttributeMaxDynamicSharedMemorySize, smem_128_o3);
    cudaFuncSetAttribute((const void*)bgemm<0, true, false, 64, 64, 3>,  cudaFuncAttributeMaxDynamicSharedMemorySize, smem_64_o3);
    cudaFuncSetAttribute((const void*)attn2, cudaFuncAttributeMaxDynamicSharedMemorySize, SMEM_ATT2);

    // launch 1: split qkv+o weights
    wsplit4<<<dim3(256, 4), 256>>>(wq, wk, wv, wo,
                                   p_wqh, p_wql, p_wkh, p_wkl,
                                   p_wvh, p_wvl, p_woh, p_wol);
    // launch 2: LN1
    ln_kernel<<<T_SEQ, 256>>>(x, g1, be1, p_xnh, p_xnl);
    // launch 3: split ffn weights
    wsplit2<<<dim3(1024, 2), 256>>>(w1, w2, p_w1h, p_w1l, p_w2h, p_w2l);

    // launch 4: fused QKV (BM=128, 3 CTAs/SM)  <-- profiled position
    bgemm<0, false, true, 128, 64, 3><<<dim3(D_MODEL / 64, T_SEQ / 128, 3), 256, smem_128_o3>>>(
        p_xnh, p_xnl, p_wqh, p_wql, p_wkh, p_wkl, p_wvh, p_wvl,
        bq, bk, bv, nullptr, p_qh, p_kh, p_vh, p_ql, p_kl, p_vl, D_MODEL, D_MODEL);

    // launch 5: attention
    attn2<<<dim3(32, N_HEADS), 256, SMEM_ATT2>>>(p_qh, p_ql, p_kh, p_kl, p_vh, p_vl, p_ah, p_al);

    // launch 6: O projection + residual(x) (BM=64 -> 512 CTAs)
    bgemm<0, true, false, 64, 64, 3><<<dim3(D_MODEL / 64, T_SEQ / 64, 1), 256, smem_64_o3>>>(
        p_ah, p_al, p_woh, p_wol, p_woh, p_wol, p_woh, p_wol,
        bo, bo, bo, x, p_x1, p_x1, p_x1, nullptr, nullptr, nullptr, D_MODEL, D_MODEL);

    // launch 7: LN2
    ln_kernel<<<T_SEQ, 256>>>(p_x1, g2, be2, p_xnh, p_xnl);

    // launch 8: FFN1 + GELU (BM=128, 1024 CTAs)
    bgemm<1, false, true, 128, 64, 3><<<dim3(FFN_DIM / 64, T_SEQ / 128, 1), 256, smem_128_o3>>>(
        p_xnh, p_xnl, p_w1h, p_w1l, p_w1h, p_w1l, p_w1h, p_w1l,
        b1, b1, b1, nullptr, p_hh, p_hh, p_hh, p_hl, p_hl, p_hl, FFN_DIM, D_MODEL);

    // launch 9: FFN2 + residual(x1) (BM=64 -> 512 CTAs)
    bgemm<0, true, false, 64, 64, 3><<<dim3(D_MODEL / 64, T_SEQ / 64, 1), 256, smem_64_o3>>>(
        p_hh, p_hl, p_w2h, p_w2l, p_w2h, p_w2l, p_w2h, p_w2l,
        b2, b2, b2, p_x1, out, out, out, nullptr, nullptr, nullptr, D_MODEL, FFN_DIM);
}

// round 17
// speedup vs baseline: 1.0417x; 1.0417x over previous
#include <cuda_runtime.h>
#include <cuda_bf16.h>
#include <math.h>
#include <stdint.h>

#define T_SEQ 2048
#define D_MODEL 1024
#define N_HEADS 16
#define HEAD_DIM 64
#define FFN_DIM 4096
typedef __nv_bfloat16 bf16;

// ---------------- scratch ----------------
__device__ float g_x1[T_SEQ * D_MODEL];
__device__ float g_part[4 * T_SEQ * D_MODEL];   // split-K partials (32MB)
__device__ bf16  g_xnh[T_SEQ * D_MODEL], g_xnl[T_SEQ * D_MODEL];
__device__ bf16  g_qh[T_SEQ * D_MODEL], g_ql[T_SEQ * D_MODEL];
__device__ bf16  g_kh[T_SEQ * D_MODEL], g_kl[T_SEQ * D_MODEL];
__device__ bf16  g_vh[T_SEQ * D_MODEL], g_vl[T_SEQ * D_MODEL];
__device__ bf16  g_ah[T_SEQ * D_MODEL], g_al[T_SEQ * D_MODEL];
__device__ bf16  g_hh[T_SEQ * FFN_DIM], g_hl[T_SEQ * FFN_DIM];
__device__ bf16 g_wqh[D_MODEL * D_MODEL], g_wql[D_MODEL * D_MODEL];
__device__ bf16 g_wkh[D_MODEL * D_MODEL], g_wkl[D_MODEL * D_MODEL];
__device__ bf16 g_wvh[D_MODEL * D_MODEL], g_wvl[D_MODEL * D_MODEL];
__device__ bf16 g_woh[D_MODEL * D_MODEL], g_wol[D_MODEL * D_MODEL];
__device__ bf16 g_w1h[FFN_DIM * D_MODEL], g_w1l[FFN_DIM * D_MODEL];
__device__ bf16 g_w2h[D_MODEL * FFN_DIM], g_w2l[D_MODEL * FFN_DIM];

// ---------------- helpers ----------------
__device__ __forceinline__ uint32_t smem_u32(const void* p) {
    uint32_t a;
    asm("{ .reg .u64 t; cvta.to.shared.u64 t, %1; cvt.u32.u64 %0, t; }" : "=r"(a) : "l"(p));
    return a;
}
__device__ __forceinline__ void cp16(uint32_t s, const void* g) {
    asm volatile("cp.async.cg.shared.global [%0], [%1], 16;" :: "r"(s), "l"(g));
}
#define CP_COMMIT() asm volatile("cp.async.commit_group;" ::: "memory")
#define CP_WAIT(n)  asm volatile("cp.async.wait_group %0;" :: "n"(n) : "memory")

__device__ __forceinline__ void ldsm4(uint32_t* r, uint32_t addr) {
    asm volatile("ldmatrix.sync.aligned.m8n8.x4.shared.b16 {%0,%1,%2,%3}, [%4];"
        : "=r"(r[0]), "=r"(r[1]), "=r"(r[2]), "=r"(r[3]) : "r"(addr));
}
__device__ __forceinline__ void ldsm4t(uint32_t* r, uint32_t addr) {
    asm volatile("ldmatrix.sync.aligned.m8n8.x4.trans.shared.b16 {%0,%1,%2,%3}, [%4];"
        : "=r"(r[0]), "=r"(r[1]), "=r"(r[2]), "=r"(r[3]) : "r"(addr));
}
__device__ __forceinline__ void mma_bf16(float* d, const uint32_t* a, const uint32_t* b) {
    asm volatile(
        "mma.sync.aligned.m16n8k16.row.col.f32.bf16.bf16.f32 "
        "{%0,%1,%2,%3}, {%4,%5,%6,%7}, {%8,%9}, {%0,%1,%2,%3};"
        : "+f"(d[0]), "+f"(d[1]), "+f"(d[2]), "+f"(d[3])
        : "r"(a[0]), "r"(a[1]), "r"(a[2]), "r"(a[3]), "r"(b[0]), "r"(b[1]));
}
__device__ __forceinline__ uint32_t bfpack(float a, float b) {
    __nv_bfloat162 t = __floats2bfloat162_rn(a, b);
    return *reinterpret_cast<uint32_t*>(&t);
}
__device__ __forceinline__ float bfhi(float v) {
    return __bfloat162float(__float2bfloat16(v));
}
__device__ __forceinline__ float ex2(float x) {
    float y;
    asm("ex2.approx.ftz.f32 %0, %1;" : "=f"(y) : "f"(x));
    return y;
}

// ---------------- batched weight splits ----------------
__global__ void wsplit4(const float* __restrict__ Wq, const float* __restrict__ Wk,
                        const float* __restrict__ Wv, const float* __restrict__ Wo,
                        bf16* __restrict__ Hq, bf16* __restrict__ Lq,
                        bf16* __restrict__ Hk, bf16* __restrict__ Lk,
                        bf16* __restrict__ Hv, bf16* __restrict__ Lv,
                        bf16* __restrict__ Ho, bf16* __restrict__ Lo) {
    const int m = blockIdx.y;
    const float* W = (m == 0) ? Wq : (m == 1) ? Wk : (m == 2) ? Wv : Wo;
    bf16* H = (m == 0) ? Hq : (m == 1) ? Hk : (m == 2) ? Hv : Ho;
    bf16* L = (m == 0) ? Lq : (m == 1) ? Lk : (m == 2) ? Lv : Lo;
    const size_t base = ((size_t)blockIdx.x * 4096) + threadIdx.x * 4;
    float4 v[4];
    #pragma unroll
    for (int j = 0; j < 4; ++j) v[j] = *(const float4*)&W[base + j * 1024];
    #pragma unroll
    for (int j = 0; j < 4; ++j) {
        uint2 hh, ll;
        hh.x = bfpack(v[j].x, v[j].y); hh.y = bfpack(v[j].z, v[j].w);
        ll.x = bfpack(v[j].x - bfhi(v[j].x), v[j].y - bfhi(v[j].y));
        ll.y = bfpack(v[j].z - bfhi(v[j].z), v[j].w - bfhi(v[j].w));
        *(uint2*)&H[base + j * 1024] = hh;
        *(uint2*)&L[base + j * 1024] = ll;
    }
}
__global__ void wsplit2(const float* __restrict__ W1, const float* __restrict__ W2,
                        bf16* __restrict__ H1, bf16* __restrict__ L1,
                        bf16* __restrict__ H2, bf16* __restrict__ L2) {
    const int m = blockIdx.y;
    const float* W = (m == 0) ? W1 : W2;
    bf16* H = (m == 0) ? H1 : H2;
    bf16* L = (m == 0) ? L1 : L2;
    const size_t base = ((size_t)blockIdx.x * 4096) + threadIdx.x * 4;
    float4 v[4];
    #pragma unroll
    for (int j = 0; j < 4; ++j) v[j] = *(const float4*)&W[base + j * 1024];
    #pragma unroll
    for (int j = 0; j < 4; ++j) {
        uint2 hh, ll;
        hh.x = bfpack(v[j].x, v[j].y); hh.y = bfpack(v[j].z, v[j].w);
        ll.x = bfpack(v[j].x - bfhi(v[j].x), v[j].y - bfhi(v[j].y));
        ll.y = bfpack(v[j].z - bfhi(v[j].z), v[j].w - bfhi(v[j].w));
        *(uint2*)&H[base + j * 1024] = hh;
        *(uint2*)&L[base + j * 1024] = ll;
    }
}

// ---------------- split-K reducers: out = sum(parts) + bias + res ----------------
template<int S>
__global__ void kreduce(const float* __restrict__ P, const float* __restrict__ bias,
                        const float* __restrict__ Res, float* __restrict__ Out) {
    const size_t i = ((size_t)blockIdx.x * 256 + threadIdx.x) * 4;
    float4 a = *(const float4*)&P[i];
    #pragma unroll
    for (int s = 1; s < S; ++s) {
        const float4 b = *(const float4*)&P[(size_t)s * T_SEQ * D_MODEL + i];
        a.x += b.x; a.y += b.y; a.z += b.z; a.w += b.w;
    }
    const float4 bv = *(const float4*)&bias[i & 1023];
    const float4 rv = *(const float4*)&Res[i];
    float4 o;
    o.x = a.x + bv.x + rv.x; o.y = a.y + bv.y + rv.y;
    o.z = a.z + bv.z + rv.z; o.w = a.w + bv.w + rv.w;
    *(float4*)&Out[i] = o;
}

// ---------------- LayerNorm -> bf16 hi/lo ----------------
__global__ void ln_kernel(const float* __restrict__ x, const float* __restrict__ g,
                          const float* __restrict__ b, bf16* __restrict__ yh,
                          bf16* __restrict__ yl) {
    const int row = blockIdx.x, tid = threadIdx.x;
    const float4 xv = *(const float4*)&x[(size_t)row * D_MODEL + tid * 4];
    float s  = (xv.x + xv.y) + (xv.z + xv.w);
    float s2 = (xv.x * xv.x + xv.y * xv.y) + (xv.z * xv.z + xv.w * xv.w);
    __shared__ float red0[8], red1[8];
    #pragma unroll
    for (int o = 16; o > 0; o >>= 1) {
        s  += __shfl_down_sync(0xffffffffu, s, o);
        s2 += __shfl_down_sync(0xffffffffu, s2, o);
    }
    const int w = tid >> 5, l = tid & 31;
    if (l == 0) { red0[w] = s; red1[w] = s2; }
    __syncthreads();
    if (w == 0) {
        s  = (l < 8) ? red0[l] : 0.f;
        s2 = (l < 8) ? red1[l] : 0.f;
        #pragma unroll
        for (int o = 4; o > 0; o >>= 1) {
            s  += __shfl_down_sync(0xffffffffu, s, o);
            s2 += __shfl_down_sync(0xffffffffu, s2, o);
        }
        if (l == 0) { red0[0] = s; red1[0] = s2; }
    }
    __syncthreads();
    const float mu  = red0[0] * (1.f / D_MODEL);
    const float var = red1[0] * (1.f / D_MODEL) - mu * mu;
    const float inv = rsqrtf(var + 1e-5f);
    const float4 gv = *(const float4*)&g[tid * 4];
    const float4 bv = *(const float4*)&b[tid * 4];
    float o0 = (xv.x - mu) * inv * gv.x + bv.x;
    float o1 = (xv.y - mu) * inv * gv.y + bv.y;
    float o2 = (xv.z - mu) * inv * gv.z + bv.z;
    float o3 = (xv.w - mu) * inv * gv.w + bv.w;
    uint2 H, L;
    H.x = bfpack(o0, o1); H.y = bfpack(o2, o3);
    L.x = bfpack(o0 - bfhi(o0), o1 - bfhi(o1));
    L.y = bfpack(o2 - bfhi(o2), o3 - bfhi(o3));
    *(uint2*)&yh[(size_t)row * D_MODEL + tid * 4] = H;
    *(uint2*)&yl[(size_t)row * D_MODEL + tid * 4] = L;
}

// ---------------- bf16x3 mma GEMM with ldmatrix (BM=128) ----------------
// OCC=2: BN=64->KB=64+DUAL. OCC=3: KB=32, no DUAL, <=85 regs.
// SPLITK>1: blockIdx.z = k-slice; raw fp32 partials to C0 + z*M*N; no bias/act/res.
template<int ACT, bool HAS_RES, bool OUT_HILO, int BN, int OCC, int SPLITK>
__global__ void __launch_bounds__(256, OCC)
bgemm(const bf16* __restrict__ Ah, const bf16* __restrict__ Al,
      const bf16* __restrict__ W0h, const bf16* __restrict__ W0l,
      const bf16* __restrict__ W1h, const bf16* __restrict__ W1l,
      const bf16* __restrict__ W2h, const bf16* __restrict__ W2l,
      const float* __restrict__ b0, const float* __restrict__ b1, const float* __restrict__ b2,
      const float* __restrict__ Res,
      void* __restrict__ C0, void* __restrict__ C1, void* __restrict__ C2,
      void* __restrict__ Cl0, void* __restrict__ Cl1, void* __restrict__ Cl2,
      int N, int K, int KLEN) {
    constexpr int KB     = (BN == 128) ? 32 : ((OCC == 3) ? 32 : 64);
    constexpr int KSTEPS = KB / 16;
    constexpr int A_STR  = KB * 2 + 16;
    constexpr int B_STR  = BN * 2 + 16;
    constexpr int ARR_A  = 128 * A_STR;
    constexpr int ARR_B  = KB * B_STR;
    constexpr int STAGE  = 2 * ARR_A + 2 * ARR_B;
    constexpr int NT     = BN / 16;
    constexpr int NPAIR  = NT / 2;
    constexpr bool DUAL  = (NT <= 4) && (OCC == 2);

    extern __shared__ char smem[];
    const int z = blockIdx.z;
    const bf16* Wh    = (SPLITK > 1 || z == 0) ? W0h : (z == 1) ? W1h : W2h;
    const bf16* Wl    = (SPLITK > 1 || z == 0) ? W0l : (z == 1) ? W1l : W2l;
    const float* bias = (z == 0) ? b0 : (z == 1) ? b1 : b2;
    void* Cv          = (z == 0) ? C0 : (z == 1) ? C1 : C2;
    void* Clv         = (z == 0) ? Cl0 : (z == 1) ? Cl1 : Cl2;
    const int kbase   = (SPLITK > 1) ? z * KLEN : 0;

    const int m0 = blockIdx.y * 128;
    const int n0 = blockIdx.x * BN;
    const int tid = threadIdx.x;
    const int wid = tid >> 5, lane = tid & 31;
    const int wrow = wid & 3, wcol = wid >> 2;
    const int lr = lane >> 2, lc = lane & 3;
    const int lrow = lane & 7, sub = lane >> 3;

    const uint32_t sbase = smem_u32(smem);
    const int NKB = KLEN / KB;

    const uint32_t aoff = (uint32_t)(wrow * 32 + lrow + 8 * (sub & 1)) * (uint32_t)A_STR + 16u * (sub >> 1);
    const uint32_t boff = (uint32_t)(lrow + 8 * (sub & 1)) * (uint32_t)B_STR +
                          (uint32_t)(wcol * (BN / 2) + 8 * (sub >> 1)) * 2u;

    auto load_stage = [&](int kb, int s) {
        const int k0 = kbase + kb * KB;
        const uint32_t st = sbase + s * STAGE;
        #pragma unroll
        for (int f = tid; f < 128 * (KB / 8); f += 256) {
            const int r = f / (KB / 8), cc = f % (KB / 8);
            const uint32_t doff = (uint32_t)r * (uint32_t)A_STR + (uint32_t)cc * 16u;
            const size_t go = (size_t)(m0 + r) * K + k0 + cc * 8;
            cp16(st + doff, Ah + go);
            cp16(st + ARR_A + doff, Al + go);
        }
        #pragma unroll
        for (int f = tid; f < KB * (BN / 8); f += 256) {
            const int r = f / (BN / 8), cc = f % (BN / 8);
            const uint32_t doff = (uint32_t)r * (uint32_t)B_STR + (uint32_t)cc * 16u;
            const size_t go = (size_t)(k0 + r) * N + n0 + cc * 8;
            cp16(st + 2 * ARR_A + doff, Wh + go);
            cp16(st + 2 * ARR_A + ARR_B + doff, Wl + go);
        }
    };

    float acc[2][NT][4];
    float accx[DUAL ? 2 : 1][DUAL ? NT : 1][4];
    #pragma unroll
    for (int mt = 0; mt < 2; ++mt)
        #pragma unroll
        for (int nt = 0; nt < NT; ++nt)
            #pragma unroll
            for (int i = 0; i < 4; ++i) {
                acc[mt][nt][i] = 0.f;
                if (DUAL) accx[mt][nt][i] = 0.f;
            }

    auto domma = [&](int s) {
        const uint32_t stg = sbase + s * STAGE;
        #pragma unroll
        for (int kstep = 0; kstep < KSTEPS; ++kstep) {
            uint32_t ah[2][4], al[2][4];
            #pragma unroll
            for (int mt = 0; mt < 2; ++mt) {
                ldsm4(ah[mt], stg + aoff + mt * 16 * A_STR + kstep * 32);
                ldsm4(al[mt], stg + ARR_A + aoff + mt * 16 * A_STR + kstep * 32);
            }
            uint32_t bh[NT][2], bl[NT][2];
            #pragma unroll
            for (int p = 0; p < NPAIR; ++p) {
                uint32_t t[4];
                ldsm4t(t, stg + 2 * ARR_A + boff + p * 32 + kstep * 16 * B_STR);
                bh[2 * p][0] = t[0]; bh[2 * p][1] = t[1];
                bh[2 * p + 1][0] = t[2]; bh[2 * p + 1][1] = t[3];
                ldsm4t(t, stg + 2 * ARR_A + ARR_B + boff + p * 32 + kstep * 16 * B_STR);
                bl[2 * p][0] = t[0]; bl[2 * p][1] = t[1];
                bl[2 * p + 1][0] = t[2]; bl[2 * p + 1][1] = t[3];
            }
            #pragma unroll
            for (int nt = 0; nt < NT; ++nt) {
                if (DUAL) {
                    mma_bf16(acc[0][nt],  ah[0], bh[nt]);
                    mma_bf16(acc[1][nt],  ah[1], bh[nt]);
                    mma_bf16(accx[0][nt], al[0], bh[nt]);
                    mma_bf16(accx[1][nt], al[1], bh[nt]);
                    mma_bf16(accx[0][nt], ah[0], bl[nt]);
                    mma_bf16(accx[1][nt], ah[1], bl[nt]);
                } else {
                    mma_bf16(acc[0][nt], ah[0], bh[nt]);
                    mma_bf16(acc[1][nt], ah[1], bh[nt]);
                    mma_bf16(acc[0][nt], al[0], bh[nt]);
                    mma_bf16(acc[1][nt], al[1], bh[nt]);
                    mma_bf16(acc[0][nt], ah[0], bl[nt]);
                    mma_bf16(acc[1][nt], ah[1], bl[nt]);
                }
            }
        }
    };

    load_stage(0, 0);
    CP_COMMIT();
    for (int kb = 0; kb < NKB; ++kb) {
        const int s = kb & 1;
        CP_WAIT(0);
        __syncthreads();
        if (kb + 1 < NKB) {
            load_stage(kb + 1, s ^ 1);
            CP_COMMIT();
        }
        domma(s);
    }

    if (DUAL) {
        #pragma unroll
        for (int mt = 0; mt < 2; ++mt)
            #pragma unroll
            for (int nt = 0; nt < NT; ++nt)
                #pragma unroll
                for (int i = 0; i < 4; ++i)
                    acc[mt][nt][i] += accx[mt][nt][i];
    }

    if (SPLITK > 1) {
        float* P = (float*)C0 + (size_t)z * T_SEQ * N;
        #pragma unroll
        for (int nt = 0; nt < NT; ++nt) {
            const int col = n0 + wcol * (BN / 2) + nt * 8 + lc * 2;
            #pragma unroll
            for (int mt = 0; mt < 2; ++mt) {
                const int row = m0 + wrow * 32 + mt * 16 + lr;
                #pragma unroll
                for (int half = 0; half < 2; ++half) {
                    const int r = row + half * 8;
                    float2 o;
                    o.x = acc[mt][nt][half * 2 + 0];
                    o.y = acc[mt][nt][half * 2 + 1];
                    *(float2*)&P[(size_t)r * N + col] = o;
                }
            }
        }
        return;
    }

    #pragma unroll
    for (int nt = 0; nt < NT; ++nt) {
        const int col = n0 + wcol * (BN / 2) + nt * 8 + lc * 2;
        const float2 bv = *(const float2*)&bias[col];
        #pragma unroll
        for (int mt = 0; mt < 2; ++mt) {
            const int row = m0 + wrow * 32 + mt * 16 + lr;
            #pragma unroll
            for (int half = 0; half < 2; ++half) {
                const int r = row + half * 8;
                float vx = acc[mt][nt][half * 2 + 0] + bv.x;
                float vy = acc[mt][nt][half * 2 + 1] + bv.y;
                if (ACT == 1) {
                    vx = 0.5f * vx * (1.0f + erff(vx * 0.7071067811865475f));
                    vy = 0.5f * vy * (1.0f + erff(vy * 0.7071067811865475f));
                }
                if (HAS_RES) {
                    float2 rv = *(const float2*)&Res[(size_t)r * N + col];
                    vx += rv.x; vy += rv.y;
                }
                if (OUT_HILO) {
                    bf16* Ch = (bf16*)Cv;
                    bf16* Cl = (bf16*)Clv;
                    *(uint32_t*)&Ch[(size_t)r * N + col] = bfpack(vx, vy);
                    *(uint32_t*)&Cl[(size_t)r * N + col] =
                        bfpack(vx - bfhi(vx), vy - bfhi(vy));
                } else {
                    float2 o; o.x = vx; o.y = vy;
                    *(float2*)&((float*)Cv)[(size_t)r * N + col] = o;
                }
            }
        }
    }
}

// ---------------- flash attention v4: 64-row q-tiles, 2 CTAs/SM ----------------
#define AS_KH(s)  ((s) * 36864 + 0)
#define AS_KL(s)  ((s) * 36864 + 9216)
#define AS_VH(s)  ((s) * 36864 + 18432)
#define AS_VL(s)  ((s) * 36864 + 27648)
#define AS_QH     73728
#define AS_QL     82944
#define AS_PMAX   92160
#define SMEM_ATT2 93184

__global__ void __launch_bounds__(256, 2)
attn2(const bf16* __restrict__ Qh, const bf16* __restrict__ Ql,
      const bf16* __restrict__ Kh, const bf16* __restrict__ Kl,
      const bf16* __restrict__ Vh, const bf16* __restrict__ Vl,
      bf16* __restrict__ OH, bf16* __restrict__ OL) {
    extern __shared__ char smc[];
    const uint32_t sb = smem_u32(smc);
    const int qb = gridDim.x - 1 - blockIdx.x;
    const int h  = blockIdx.y;
    const int tid = threadIdx.x;
    const int wid = tid >> 5, lane = tid & 31;
    const int wrow = wid & 1, wcol = wid >> 1;
    const int lr = lane >> 2, lc = lane & 3;
    const int lrow = lane & 7, sub = lane >> 3;

    float* pmax = (float*)(smc + AS_PMAX);

    #pragma unroll
    for (int i = 0; i < 2; ++i) {
        const int f = tid + i * 256;
        const int r = f >> 3, c = f & 7;
        const size_t go = (size_t)(qb * 64 + r) * D_MODEL + h * 64 + c * 8;
        cp16(sb + AS_QH + r * 144 + c * 16, Qh + go);
        cp16(sb + AS_QL + r * 144 + c * 16, Ql + go);
    }
    auto load_kv = [&](int kb, int s) {
        #pragma unroll
        for (int i = 0; i < 2; ++i) {
            const int f = tid + i * 256;
            const int r = f >> 3, c = f & 7;
            const size_t go = (size_t)(kb * 64 + r) * D_MODEL + h * 64 + c * 8;
            cp16(sb + AS_KH(s) + r * 144 + c * 16, Kh + go);
            cp16(sb + AS_KL(s) + r * 144 + c * 16, Kl + go);
            cp16(sb + AS_VH(s) + r * 144 + c * 16, Vh + go);
            cp16(sb + AS_VL(s) + r * 144 + c * 16, Vl + go);
        }
    };
    load_kv(0, 0);
    CP_COMMIT();

    const float QS = 0.125f * 1.4426950408889634f;
    const float slope2 = 1.4426950408889634f * exp2f(-0.5f * (float)(h + 1));
    float oacc[2][8][4] = {};
    float m_reg[2][2] = {{-1e30f, -1e30f}, {-1e30f, -1e30f}};
    float l_reg[2][2] = {};

    const uint32_t aoffQ = sb + AS_QH + (uint32_t)(wrow * 32 + lrow + 8 * (sub & 1)) * 144u + 16u * (sub >> 1);
    const uint32_t bSoff = (uint32_t)(16 * wcol + lrow + 8 * (sub >> 1)) * 144u + 16u * (sub & 1);
    const uint32_t bVoff = (uint32_t)(16 * wcol + lrow + 8 * (sub & 1)) * 144u + (uint32_t)(8 * (sub >> 1)) * 2u;

    const int nkb = qb + 1;
    for (int kb = 0; kb < nkb; ++kb) {
        const int s = kb & 1;
        CP_WAIT(0);
        __syncthreads();
        if (kb + 1 < nkb) { load_kv(kb + 1, s ^ 1); CP_COMMIT(); }

        float sacc[2][2][4] = {};
        #pragma unroll
        for (int ks = 0; ks < 4; ++ks) {
            uint32_t qhf[2][4], qlf[2][4];
            #pragma unroll
            for (int mt = 0; mt < 2; ++mt) {
                ldsm4(qhf[mt], aoffQ + mt * 2304 + ks * 32);
                ldsm4(qlf[mt], aoffQ + 9216 + mt * 2304 + ks * 32);
            }
            uint32_t khf[2][2], klf[2][2], t[4];
            ldsm4(t, sb + AS_KH(s) + bSoff + ks * 32);
            khf[0][0] = t[0]; khf[0][1] = t[1]; khf[1][0] = t[2]; khf[1][1] = t[3];
            ldsm4(t, sb + AS_KL(s) + bSoff + ks * 32);
            klf[0][0] = t[0]; klf[0][1] = t[1]; klf[1][0] = t[2]; klf[1][1] = t[3];
            #pragma unroll
            for (int nt = 0; nt < 2; ++nt) {
                mma_bf16(sacc[0][nt], qhf[0], khf[nt]);
                mma_bf16(sacc[1][nt], qhf[1], khf[nt]);
                mma_bf16(sacc[0][nt], qlf[0], khf[nt]);
                mma_bf16(sacc[1][nt], qlf[1], khf[nt]);
                mma_bf16(sacc[0][nt], qhf[0], klf[nt]);
                mma_bf16(sacc[1][nt], qhf[1], klf[nt]);
            }
        }

        const bool diag = (kb == qb);
        #pragma unroll
        for (int mt = 0; mt < 2; ++mt) {
            const int ra = qb * 64 + wrow * 32 + mt * 16 + lr, rb = ra + 8;
            float ma = -1e30f, mb = -1e30f;
            #pragma unroll
            for (int nt = 0; nt < 2; ++nt) {
                const int c0 = kb * 64 + 16 * wcol + 8 * nt + 2 * lc;
                float* sv = sacc[mt][nt];
                if (diag) {
                    sv[0] = (c0     <= ra) ? fmaf(sv[0], QS, slope2 * (float)(c0 - ra))     : -1e30f;
                    sv[1] = (c0 + 1 <= ra) ? fmaf(sv[1], QS, slope2 * (float)(c0 + 1 - ra)) : -1e30f;
                    sv[2] = (c0     <= rb) ? fmaf(sv[2], QS, slope2 * (float)(c0 - rb))     : -1e30f;
                    sv[3] = (c0 + 1 <= rb) ? fmaf(sv[3], QS, slope2 * (float)(c0 + 1 - rb)) : -1e30f;
                } else {
                    sv[0] = fmaf(sv[0], QS, slope2 * (float)(c0 - ra));
                    sv[1] = fmaf(sv[1], QS, slope2 * (float)(c0 + 1 - ra));
                    sv[2] = fmaf(sv[2], QS, slope2 * (float)(c0 - rb));
                    sv[3] = fmaf(sv[3], QS, slope2 * (float)(c0 + 1 - rb));
                }
                ma = fmaxf(ma, fmaxf(sv[0], sv[1]));
                mb = fmaxf(mb, fmaxf(sv[2], sv[3]));
            }
            ma = fmaxf(ma, __shfl_xor_sync(0xffffffffu, ma, 1));
            ma = fmaxf(ma, __shfl_xor_sync(0xffffffffu, ma, 2));
            mb = fmaxf(mb, __shfl_xor_sync(0xffffffffu, mb, 1));
            mb = fmaxf(mb, __shfl_xor_sync(0xffffffffu, mb, 2));
            if (lc == 0) {
                pmax[wcol * 64 + wrow * 32 + mt * 16 + lr]     = ma;
                pmax[wcol * 64 + wrow * 32 + mt * 16 + lr + 8] = mb;
            }
        }
        __syncthreads();

        float alpha[2][2];
        #pragma unroll
        for (int mt = 0; mt < 2; ++mt) {
            const int rla = wrow * 32 + mt * 16 + lr, rlb = rla + 8;
            const float pa = fmaxf(fmaxf(pmax[rla], pmax[64 + rla]),
                                   fmaxf(pmax[128 + rla], pmax[192 + rla]));
            const float pb = fmaxf(fmaxf(pmax[rlb], pmax[64 + rlb]),
                                   fmaxf(pmax[128 + rlb], pmax[192 + rlb]));
            const float mna = fmaxf(m_reg[mt][0], pa);
            const float mnb = fmaxf(m_reg[mt][1], pb);
            alpha[mt][0] = ex2(m_reg[mt][0] - mna);
            alpha[mt][1] = ex2(m_reg[mt][1] - mnb);
            m_reg[mt][0] = mna; m_reg[mt][1] = mnb;
        }
        #pragma unroll
        for (int mt = 0; mt < 2; ++mt) {
            float sa = 0.f, sbv = 0.f;
            #pragma unroll
            for (int nt = 0; nt < 2; ++nt) {
                float* sv = sacc[mt][nt];
                sv[0] = ex2(sv[0] - m_reg[mt][0]); sv[1] = ex2(sv[1] - m_reg[mt][0]);
                sv[2] = ex2(sv[2] - m_reg[mt][1]); sv[3] = ex2(sv[3] - m_reg[mt][1]);
                sa += sv[0] + sv[1]; sbv += sv[2] + sv[3];
            }
            sa  += __shfl_xor_sync(0xffffffffu, sa, 1);
            sa  += __shfl_xor_sync(0xffffffffu, sa, 2);
            sbv += __shfl_xor_sync(0xffffffffu, sbv, 1);
            sbv += __shfl_xor_sync(0xffffffffu, sbv, 2);
            l_reg[mt][0] = l_reg[mt][0] * alpha[mt][0] + sa;
            l_reg[mt][1] = l_reg[mt][1] * alpha[mt][1] + sbv;
        }
        #pragma unroll
        for (int mt = 0; mt < 2; ++mt)
            #pragma unroll
            for (int nt = 0; nt < 8; ++nt) {
                oacc[mt][nt][0] *= alpha[mt][0]; oacc[mt][nt][1] *= alpha[mt][0];
                oacc[mt][nt][2] *= alpha[mt][1]; oacc[mt][nt][3] *= alpha[mt][1];
            }

        uint32_t pah[2][4], pal[2][4];
        #pragma unroll
        for (int mt = 0; mt < 2; ++mt) {
            const float* s0 = sacc[mt][0];
            const float* s1 = sacc[mt][1];
            pah[mt][0] = bfpack(s0[0], s0[1]); pah[mt][1] = bfpack(s0[2], s0[3]);
            pah[mt][2] = bfpack(s1[0], s1[1]); pah[mt][3] = bfpack(s1[2], s1[3]);
            pal[mt][0] = bfpack(s0[0] - bfhi(s0[0]), s0[1] - bfhi(s0[1]));
            pal[mt][1] = bfpack(s0[2] - bfhi(s0[2]), s0[3] - bfhi(s0[3]));
            pal[mt][2] = bfpack(s1[0] - bfhi(s1[0]), s1[1] - bfhi(s1[1]));
            pal[mt][3] = bfpack(s1[2] - bfhi(s1[2]), s1[3] - bfhi(s1[3]));
        }
        #pragma unroll
        for (int p = 0; p < 4; ++p) {
            uint32_t vh[2][2], vl[2][2], t[4];
            ldsm4t(t, sb + AS_VH(s) + bVoff + p * 32);
            vh[0][0] = t[0]; vh[0][1] = t[1]; vh[1][0] = t[2]; vh[1][1] = t[3];
            ldsm4t(t, sb + AS_VL(s) + bVoff + p * 32);
            vl[0][0] = t[0]; vl[0][1] = t[1]; vl[1][0] = t[2]; vl[1][1] = t[3];
            #pragma unroll
            for (int q2 = 0; q2 < 2; ++q2) {
                const int nt = 2 * p + q2;
                mma_bf16(oacc[0][nt], pah[0], vh[q2]);
                mma_bf16(oacc[1][nt], pah[1], vh[q2]);
                mma_bf16(oacc[0][nt], pal[0], vh[q2]);
                mma_bf16(oacc[1][nt], pal[1], vh[q2]);
                mma_bf16(oacc[0][nt], pah[0], vl[q2]);
                mma_bf16(oacc[1][nt], pah[1], vl[q2]);
            }
        }
    }

    __syncthreads();
    if (lc == 0) {
        #pragma unroll
        for (int mt = 0; mt < 2; ++mt) {
            pmax[wcol * 64 + wrow * 32 + mt * 16 + lr]     = l_reg[mt][0];
            pmax[wcol * 64 + wrow * 32 + mt * 16 + lr + 8] = l_reg[mt][1];
        }
    }
    float* Ob = (float*)smc;
    #pragma unroll
    for (int w = 0; w < 4; ++w) {
        if (wcol == w) {
            #pragma unroll
            for (int mt = 0; mt < 2; ++mt) {
                const int rla = wrow * 32 + mt * 16 + lr, rlb = rla + 8;
                #pragma unroll
                for (int nt = 0; nt < 8; ++nt) {
                    const int d0 = 8 * nt + 2 * lc;
                    if (w == 0) {
                        Ob[rla * 64 + d0]     = oacc[mt][nt][0];
                        Ob[rla * 64 + d0 + 1] = oacc[mt][nt][1];
                        Ob[rlb * 64 + d0]     = oacc[mt][nt][2];
                        Ob[rlb * 64 + d0 + 1] = oacc[mt][nt][3];
                    } else {
                        Ob[rla * 64 + d0]     += oacc[mt][nt][0];
                        Ob[rla * 64 + d0 + 1] += oacc[mt][nt][1];
                        Ob[rlb * 64 + d0]     += oacc[mt][nt][2];
                        Ob[rlb * 64 + d0 + 1] += oacc[mt][nt][3];
                    }
                }
            }
        }
        __syncthreads();
    }
    #pragma unroll
    for (int i = 0; i < 16; ++i) {
        const int f = tid + i * 256;
        const int r = f >> 6, d = f & 63;
        const float lsum = (pmax[r] + pmax[64 + r]) + (pmax[128 + r] + pmax[192 + r]);
        const float val = Ob[f] / lsum;
        const size_t go = (size_t)(qb * 64 + r) * D_MODEL + h * 64 + d;
        OH[go] = __float2bfloat16(val);
        OL[go] = __float2bfloat16(val - bfhi(val));
    }
}

// ---------------- launch ----------------
extern "C" void kernel_launch(void* const* d_in, const int* in_sizes, int n_in,
                              void* d_out, int out_size) {
    const float* x   = (const float*)d_in[0];
    const float* wq  = (const float*)d_in[3];
    const float* bq  = (const float*)d_in[4];
    const float* wk  = (const float*)d_in[5];
    const float* bk  = (const float*)d_in[6];
    const float* wv  = (const float*)d_in[7];
    const float* bv  = (const float*)d_in[8];
    const float* wo  = (const float*)d_in[9];
    const float* bo  = (const float*)d_in[10];
    const float* w1  = (const float*)d_in[11];
    const float* b1  = (const float*)d_in[12];
    const float* w2  = (const float*)d_in[13];
    const float* b2  = (const float*)d_in[14];
    const float* g1  = (const float*)d_in[15];
    const float* be1 = (const float*)d_in[16];
    const float* g2  = (const float*)d_in[17];
    const float* be2 = (const float*)d_in[18];
    float* out = (float*)d_out;

    float *p_x1, *p_part;
    bf16 *p_xnh, *p_xnl, *p_ah, *p_al, *p_hh, *p_hl;
    bf16 *p_qh, *p_ql, *p_kh, *p_kl, *p_vh, *p_vl;
    bf16 *p_wqh, *p_wql, *p_wkh, *p_wkl, *p_wvh, *p_wvl, *p_woh, *p_wol;
    bf16 *p_w1h, *p_w1l, *p_w2h, *p_w2l;
    cudaGetSymbolAddress((void**)&p_x1,   g_x1);
    cudaGetSymbolAddress((void**)&p_part, g_part);
    cudaGetSymbolAddress((void**)&p_xnh, g_xnh);
    cudaGetSymbolAddress((void**)&p_xnl, g_xnl);
    cudaGetSymbolAddress((void**)&p_qh,  g_qh);
    cudaGetSymbolAddress((void**)&p_ql,  g_ql);
    cudaGetSymbolAddress((void**)&p_kh,  g_kh);
    cudaGetSymbolAddress((void**)&p_kl,  g_kl);
    cudaGetSymbolAddress((void**)&p_vh,  g_vh);
    cudaGetSymbolAddress((void**)&p_vl,  g_vl);
    cudaGetSymbolAddress((void**)&p_ah,  g_ah);
    cudaGetSymbolAddress((void**)&p_al,  g_al);
    cudaGetSymbolAddress((void**)&p_hh,  g_hh);
    cudaGetSymbolAddress((void**)&p_hl,  g_hl);
    cudaGetSymbolAddress((void**)&p_wqh, g_wqh);
    cudaGetSymbolAddress((void**)&p_wql, g_wql);
    cudaGetSymbolAddress((void**)&p_wkh, g_wkh);
    cudaGetSymbolAddress((void**)&p_wkl, g_wkl);
    cudaGetSymbolAddress((void**)&p_wvh, g_wvh);
    cudaGetSymbolAddress((void**)&p_wvl, g_wvl);
    cudaGetSymbolAddress((void**)&p_woh, g_woh);
    cudaGetSymbolAddress((void**)&p_wol, g_wol);
    cudaGetSymbolAddress((void**)&p_w1h, g_w1h);
    cudaGetSymbolAddress((void**)&p_w1l, g_w1l);
    cudaGetSymbolAddress((void**)&p_w2h, g_w2h);
    cudaGetSymbolAddress((void**)&p_w2l, g_w2l);

    const int smem_o3 = 2 * (2 * 128 * 80 + 2 * 32 * 144);   // 59392 (KB=32)

    cudaFuncSetAttribute((const void*)bgemm<0, false, true, 64, 3, 1>, cudaFuncAttributeMaxDynamicSharedMemorySize, smem_o3);
    cudaFuncSetAttribute((const void*)bgemm<1, false, true, 64, 3, 1>, cudaFuncAttributeMaxDynamicSharedMemorySize, smem_o3);
    cudaFuncSetAttribute((const void*)bgemm<0, false, false, 64, 3, 2>, cudaFuncAttributeMaxDynamicSharedMemorySize, smem_o3);
    cudaFuncSetAttribute((const void*)bgemm<0, false, false, 64, 3, 4>, cudaFuncAttributeMaxDynamicSharedMemorySize, smem_o3);
    cudaFuncSetAttribute((const void*)attn2, cudaFuncAttributeMaxDynamicSharedMemorySize, SMEM_ATT2);

    // launch 1: split qkv+o weights
    wsplit4<<<dim3(256, 4), 256>>>(wq, wk, wv, wo,
                                   p_wqh, p_wql, p_wkh, p_wkl,
                                   p_wvh, p_wvl, p_woh, p_wol);
    // launch 2: LN1
    ln_kernel<<<T_SEQ, 256>>>(x, g1, be1, p_xnh, p_xnl);
    // launch 3: split ffn weights
    wsplit2<<<dim3(1024, 2), 256>>>(w1, w2, p_w1h, p_w1l, p_w2h, p_w2l);

    // launch 4: fused QKV (OCC=3)  <-- profiled position
    bgemm<0, false, true, 64, 3, 1><<<dim3(D_MODEL / 64, T_SEQ / 128, 3), 256, smem_o3>>>(
        p_xnh, p_xnl, p_wqh, p_wql, p_wkh, p_wkl, p_wvh, p_wvl,
        bq, bk, bv, nullptr, p_qh, p_kh, p_vh, p_ql, p_kl, p_vl,
        D_MODEL, D_MODEL, D_MODEL);

    // launch 5: attention
    attn2<<<dim3(32, N_HEADS), 256, SMEM_ATT2>>>(p_qh, p_ql, p_kh, p_kl, p_vh, p_vl, p_ah, p_al);

    // launch 6a: O projection pass-A (split-K=2 -> 256 CTAs)
    bgemm<0, false, false, 64, 3, 2><<<dim3(D_MODEL / 64, T_SEQ / 128, 2), 256, smem_o3>>>(
        p_ah, p_al, p_woh, p_wol, nullptr, nullptr, nullptr, nullptr,
        bo, bo, bo, nullptr, p_part, nullptr, nullptr, nullptr, nullptr, nullptr,
        D_MODEL, D_MODEL, 512);
    // launch 6b: reduce + bias + residual(x) -> x1
    kreduce<2><<<T_SEQ * D_MODEL / 1024, 256>>>(p_part, bo, x, p_x1);

    // launch 7: LN2
    ln_kernel<<<T_SEQ, 256>>>(p_x1, g2, be2, p_xnh, p_xnl);

    // launch 8: FFN1 + GELU (OCC=3, 1024 CTAs)
    bgemm<1, false, true, 64, 3, 1><<<dim3(FFN_DIM / 64, T_SEQ / 128, 1), 256, smem_o3>>>(
        p_xnh, p_xnl, p_w1h, p_w1l, p_w1h, p_w1l, p_w1h, p_w1l,
        b1, b1, b1, nullptr, p_hh, p_hh, p_hh, p_hl, p_hl, p_hl,
        FFN_DIM, D_MODEL, D_MODEL);

    // launch 9a: FFN2 pass-A (split-K=4 -> 512 CTAs)
    bgemm<0, false, false, 64, 3, 4><<<dim3(D_MODEL / 64, T_SEQ / 128, 4), 256, smem_o3>>>(
        p_hh, p_hl, p_w2h, p_w2l, nullptr, nullptr, nullptr, nullptr,
        b2, b2, b2, nullptr, p_part, nullptr, nullptr, nullptr, nullptr, nullptr,
        D_MODEL, FFN_DIM, 1024);
    // launch 9b: reduce + bias + residual(x1) -> out
    kreduce<4><<<T_SEQ * D_MODEL / 1024, 256>>>(p_part, b2, p_x1, out);
}